// round 16
// baseline (speedup 1.0000x reference)
#include <cuda_runtime.h>
#include <math.h>

#define T_STEPS 16384
#define IDIM 1024
#define HDIM 1024
#define GDIM 4096
#define NBLK 128
#define RTHREADS 256
#define NGRP 8                          // barrier counter shards (R5-proven)
#define CTAS_PER_GRP (NBLK / NGRP)      // 16; shard s certifies h[128s..128s+128)

// ---------------- device globals (scratch; no allocations allowed) ------------
__device__ float g_xgates[(size_t)T_STEPS * GDIM];   // 256 MB input gates
__device__ __align__(16) float g_h[2][HDIM];         // double-buffered hidden state
__device__ unsigned g_ctr[NGRP * 32];                // 8 counters, 128B apart

// ---------------- helpers -----------------------------------------------------
static __device__ __forceinline__ unsigned long long pk2(float lo, float hi) {
    unsigned long long r;
    asm("mov.b64 %0, {%1, %2};" : "=l"(r) : "f"(lo), "f"(hi));
    return r;
}
static __device__ __forceinline__ void fma2(unsigned long long& d,
                                            unsigned long long a,
                                            unsigned long long b) {
    asm("fma.rn.f32x2 %0, %1, %2, %0;" : "+l"(d) : "l"(a), "l"(b));
}
static __device__ __forceinline__ float2 up2(unsigned long long v) {
    float2 f;
    asm("mov.b64 {%0, %1}, %2;" : "=f"(f.x), "=f"(f.y) : "l"(v));
    return f;
}
static __device__ __forceinline__ float fast_sigmoid(float x) {
    return __fdividef(1.0f, 1.0f + __expf(-x));
}
static __device__ __forceinline__ float fast_tanh(float x) {
    return 1.0f - __fdividef(2.0f, __expf(2.0f * x) + 1.0f);
}
static __device__ __forceinline__ unsigned ld_acq(const unsigned* p) {
    unsigned v;
    asm volatile("ld.acquire.gpu.u32 %0, [%1];" : "=r"(v) : "l"(p) : "memory");
    return v;
}
static __device__ __forceinline__ void red_rel(unsigned* p) {
    asm volatile("red.release.gpu.add.u32 [%0], %1;" :: "l"(p), "r"(1u) : "memory");
}
// 3xTF32 split helpers.
static __device__ __forceinline__ void tf32_split(float v, float& hi, float& lo) {
    unsigned h;
    asm("cvt.rna.tf32.f32 %0, %1;" : "=r"(h) : "f"(v));
    hi = __uint_as_float(h);
    float rem = v - hi;
    unsigned l;
    asm("cvt.rna.tf32.f32 %0, %1;" : "=r"(l) : "f"(rem));
    lo = __uint_as_float(l);
}
static __device__ __forceinline__ void mma_tf32(float* c, const unsigned* a,
                                                const unsigned* bfr) {
    asm volatile(
        "mma.sync.aligned.m16n8k8.row.col.f32.tf32.tf32.f32 "
        "{%0,%1,%2,%3}, {%4,%5,%6,%7}, {%8,%9}, {%0,%1,%2,%3};"
        : "+f"(c[0]), "+f"(c[1]), "+f"(c[2]), "+f"(c[3])
        : "r"(a[0]), "r"(a[1]), "r"(a[2]), "r"(a[3]), "r"(bfr[0]), "r"(bfr[1]));
}

// ---------------- init: reset counters each launch (graph replays!) -----------
__global__ void init_kernel() {
    int i = threadIdx.x;
    if (i < NGRP * 32) g_ctr[i] = 0u;
}

// ---------------- GEMM (3xTF32 tensor cores): xg = A @ W^T + (bih + bhh) ------
// (unchanged from R15 — part of the best kernel)
__global__ __launch_bounds__(256) void gemm_tf32_kernel(
    const float* __restrict__ A, const float* __restrict__ W,
    const float* __restrict__ bih, const float* __restrict__ bhh) {
    __shared__ float As_hi[8][132], As_lo[8][132];
    __shared__ float Bs_hi[8][132], Bs_lo[8][132];
    __shared__ float s_bias[128];

    const int tid = threadIdx.x;
    const int m0 = blockIdx.x * 128;
    const int n0 = blockIdx.y * 128;
    const int lrow = tid >> 1;          // 0..127
    const int kq = (tid & 1) * 4;       // 0 or 4
    const int warp = tid >> 5;
    const int lane = tid & 31;
    const int wm = (warp >> 1) * 32;    // warp m-offset
    const int wn = (warp & 1) * 64;     // warp n-offset
    const int kk = lane & 3;
    const int mr = lane >> 2;

    if (tid < 128) s_bias[tid] = bih[n0 + tid] + bhh[n0 + tid];

    float c[2][8][4];
#pragma unroll
    for (int im = 0; im < 2; im++)
#pragma unroll
        for (int in = 0; in < 8; in++)
#pragma unroll
            for (int i = 0; i < 4; i++) c[im][in][i] = 0.0f;

    const float* aptr = A + (size_t)(m0 + lrow) * IDIM + kq;
    const float* wptr = W + (size_t)(n0 + lrow) * IDIM + kq;
    float4 av = *(const float4*)aptr;
    float4 bv = *(const float4*)wptr;

    for (int k0 = 0; k0 < IDIM; k0 += 8) {
        __syncthreads();
        {
            float h, l;
            tf32_split(av.x, h, l); As_hi[kq + 0][lrow] = h; As_lo[kq + 0][lrow] = l;
            tf32_split(av.y, h, l); As_hi[kq + 1][lrow] = h; As_lo[kq + 1][lrow] = l;
            tf32_split(av.z, h, l); As_hi[kq + 2][lrow] = h; As_lo[kq + 2][lrow] = l;
            tf32_split(av.w, h, l); As_hi[kq + 3][lrow] = h; As_lo[kq + 3][lrow] = l;
            tf32_split(bv.x, h, l); Bs_hi[kq + 0][lrow] = h; Bs_lo[kq + 0][lrow] = l;
            tf32_split(bv.y, h, l); Bs_hi[kq + 1][lrow] = h; Bs_lo[kq + 1][lrow] = l;
            tf32_split(bv.z, h, l); Bs_hi[kq + 2][lrow] = h; Bs_lo[kq + 2][lrow] = l;
            tf32_split(bv.w, h, l); Bs_hi[kq + 3][lrow] = h; Bs_lo[kq + 3][lrow] = l;
        }
        __syncthreads();
        if (k0 + 8 < IDIM) {
            av = *(const float4*)(aptr + k0 + 8);
            bv = *(const float4*)(wptr + k0 + 8);
        }

        unsigned Ah[2][4], Al[2][4], Bh[8][2], Bl[8][2];
#pragma unroll
        for (int im = 0; im < 2; im++) {
            int mb = wm + im * 16 + mr;
            Ah[im][0] = __float_as_uint(As_hi[kk][mb]);
            Ah[im][1] = __float_as_uint(As_hi[kk][mb + 8]);
            Ah[im][2] = __float_as_uint(As_hi[kk + 4][mb]);
            Ah[im][3] = __float_as_uint(As_hi[kk + 4][mb + 8]);
            Al[im][0] = __float_as_uint(As_lo[kk][mb]);
            Al[im][1] = __float_as_uint(As_lo[kk][mb + 8]);
            Al[im][2] = __float_as_uint(As_lo[kk + 4][mb]);
            Al[im][3] = __float_as_uint(As_lo[kk + 4][mb + 8]);
        }
#pragma unroll
        for (int in = 0; in < 8; in++) {
            int nb = wn + in * 8 + mr;
            Bh[in][0] = __float_as_uint(Bs_hi[kk][nb]);
            Bh[in][1] = __float_as_uint(Bs_hi[kk + 4][nb]);
            Bl[in][0] = __float_as_uint(Bs_lo[kk][nb]);
            Bl[in][1] = __float_as_uint(Bs_lo[kk + 4][nb]);
        }

#pragma unroll
        for (int im = 0; im < 2; im++)
#pragma unroll
            for (int in = 0; in < 8; in++) {
                mma_tf32(c[im][in], Ah[im], Bh[in]);
                mma_tf32(c[im][in], Ah[im], Bl[in]);
                mma_tf32(c[im][in], Al[im], Bh[in]);
            }
    }

#pragma unroll
    for (int im = 0; im < 2; im++) {
#pragma unroll
        for (int in = 0; in < 8; in++) {
            int nloc = wn + in * 8 + 2 * (lane & 3);
            int m_lo = m0 + wm + im * 16 + mr;
            float b0 = s_bias[nloc], b1 = s_bias[nloc + 1];
            float2 v0 = make_float2(c[im][in][0] + b0, c[im][in][1] + b1);
            float2 v1 = make_float2(c[im][in][2] + b0, c[im][in][3] + b1);
            *(float2*)&g_xgates[(size_t)m_lo * GDIM + n0 + nloc] = v0;
            *(float2*)&g_xgates[(size_t)(m_lo + 8) * GDIM + n0 + nloc] = v1;
        }
    }
}

// ---------------- persistent LSTM recurrence (split-phase consumption) --------
// R5/R15 protocol unchanged (same counters, targets, release/acquire chain).
// NEW: the step is consumed in two half-phases, overlapping the lower half's
// staging+FMA with the (possible) upper-shard straggler:
//   poll shards 0..3 -> stage h[0:512] -> FMA c0=0..15
//   poll shards 4..7 -> stage h[512:1024] -> FMA c0=16..31 -> reduce/epilogue
// Shard s certifies exactly h[128s..128s+128) (CTA b -> elements 8b..8b+7,
// shard = b>>4), so phase A touches only shard-0..3 data. Overwrite safety:
// unchanged — both polls for step t precede any CTA's step-t arrival, so
// h(t+1) stores (and the t+1 refill, gated by poll-A(t+1)) cannot race
// readers of h(t). Barrier sequence is uniform across the CTA.
__global__ __launch_bounds__(RTHREADS, 1) void lstm_kernel(const float* __restrict__ Whh) {
    __shared__ __align__(16) float sh_h[HDIM];

    const int tid = threadIdx.x;
    const int w = tid >> 5;             // warp 0..7
    const int lane = tid & 31;
    const int b = blockIdx.x;           // 0..127
    const int e = b * 8 + w;            // owned h element
    const int grp = b >> 4;             // counter shard

    unsigned long long w01[32], w23[32];
#pragma unroll
    for (int c0 = 0; c0 < 32; c0++) {
        int col = lane + 32 * c0;
        w01[c0] = pk2(Whh[(size_t)(0 * HDIM + e) * HDIM + col],
                      Whh[(size_t)(1 * HDIM + e) * HDIM + col]);
        w23[c0] = pk2(Whh[(size_t)(2 * HDIM + e) * HDIM + col],
                      Whh[(size_t)(3 * HDIM + e) * HDIM + col]);
    }

    float c_state = 0.0f;               // lane 0's value is authoritative

    for (int t = 0; t < T_STEPS; t++) {
        // Prefetch this step's 4 xg values (independent of h; hides behind wait)
        float xg0, xg1, xg2, xg3;
        if (lane == 0) {
            const float* xr = &g_xgates[(size_t)t * GDIM + e];
            xg0 = __ldcg(xr);
            xg1 = __ldcg(xr + HDIM);
            xg2 = __ldcg(xr + 2 * HDIM);
            xg3 = __ldcg(xr + 3 * HDIM);
        }

        unsigned long long acc01 = 0ULL, acc23 = 0ULL;

        // ---- Phase A: shards 0..3 -> h[0:512] -> FMA c0=0..15 ----
        if (t > 0) {
            if (w == 0) {
                const unsigned target = (unsigned)t * CTAS_PER_GRP;
                for (;;) {
                    unsigned v = target;
                    if (lane < 4) v = ld_acq(&g_ctr[lane * 32]);
                    if (__all_sync(0xffffffffu, v >= target)) break;
                }
            }
            __syncthreads();            // (a) lower shards certified
            ((float2*)sh_h)[tid] =
                __ldcg((const float2*)&g_h[t & 1][0] + tid);   // 512 floats
        } else {
            ((float2*)sh_h)[tid] = make_float2(0.f, 0.f);
        }
        __syncthreads();                // (b) lower half staged

#pragma unroll
        for (int c0 = 0; c0 < 16; c0++) {
            float hv = sh_h[lane + 32 * c0];        // bank = lane: conflict-free
            unsigned long long hh = pk2(hv, hv);
            fma2(acc01, w01[c0], hh);
            fma2(acc23, w23[c0], hh);
        }

        // ---- Phase B: shards 4..7 -> h[512:1024] -> FMA c0=16..31 ----
        if (t > 0) {
            if (w == 0) {
                const unsigned target = (unsigned)t * CTAS_PER_GRP;
                for (;;) {
                    unsigned v = target;
                    if (lane < 4) v = ld_acq(&g_ctr[(4 + lane) * 32]);
                    if (__all_sync(0xffffffffu, v >= target)) break;
                }
            }
            __syncthreads();            // (c) upper shards certified
            ((float2*)sh_h)[256 + tid] =
                __ldcg((const float2*)&g_h[t & 1][512] + tid); // 512 floats
        } else {
            ((float2*)sh_h)[256 + tid] = make_float2(0.f, 0.f);
        }
        __syncthreads();                // (d) upper half staged

#pragma unroll
        for (int c0 = 16; c0 < 32; c0++) {
            float hv = sh_h[lane + 32 * c0];
            unsigned long long hh = pk2(hv, hv);
            fma2(acc01, w01[c0], hh);
            fma2(acc23, w23[c0], hh);
        }

        float2 s01 = up2(acc01), s23 = up2(acc23);
#pragma unroll
        for (int off = 16; off; off >>= 1) {
            s01.x += __shfl_xor_sync(0xffffffffu, s01.x, off);
            s01.y += __shfl_xor_sync(0xffffffffu, s01.y, off);
            s23.x += __shfl_xor_sync(0xffffffffu, s23.x, off);
            s23.y += __shfl_xor_sync(0xffffffffu, s23.y, off);
        }

        if (lane == 0) {
            float i_ = fast_sigmoid(s01.x + xg0);
            float f_ = fast_sigmoid(s01.y + xg1);
            float g_ = fast_tanh(s23.x + xg2);
            float o_ = fast_sigmoid(s23.y + xg3);
            c_state = f_ * c_state + i_ * g_;
            float hn = o_ * fast_tanh(c_state);
            __stcg(&g_h[(t + 1) & 1][e], hn);
        }
        __syncthreads();                // (e) all 8 h-stores issued; also gates
                                        //     next step's sh_h refill
        if (tid == 0) red_rel(&g_ctr[grp * 32]);
    }
}

// ---------------- final: out = W_lin @ h_last + b_lin -------------------------
__global__ void final_kernel(const float* __restrict__ Wl,
                             const float* __restrict__ bl,
                             float* __restrict__ out) {
    __shared__ float partial[32];
    const int tid = threadIdx.x;     // 1024 threads
    float v = Wl[tid] * g_h[0][tid]; // h(T) lives in buffer (T_STEPS & 1) == 0
#pragma unroll
    for (int off = 16; off; off >>= 1) v += __shfl_xor_sync(0xffffffffu, v, off);
    if ((tid & 31) == 0) partial[tid >> 5] = v;
    __syncthreads();
    if (tid < 32) {
        float s = partial[tid];
#pragma unroll
        for (int off = 16; off; off >>= 1) s += __shfl_xor_sync(0xffffffffu, s, off);
        if (tid == 0) out[0] = s + bl[0];
    }
}

// ---------------- launch -------------------------------------------------------
extern "C" void kernel_launch(void* const* d_in, const int* in_sizes, int n_in,
                              void* d_out, int out_size) {
    const float* input = (const float*)d_in[0];   // [T, I]
    const float* W_ih  = (const float*)d_in[1];   // [4H, I]
    const float* W_hh  = (const float*)d_in[2];   // [4H, H]
    const float* b_ih  = (const float*)d_in[3];   // [4H]
    const float* b_hh  = (const float*)d_in[4];   // [4H]
    const float* W_lin = (const float*)d_in[5];   // [1, H]
    const float* b_lin = (const float*)d_in[6];   // [1]
    float* out = (float*)d_out;

    init_kernel<<<1, 256>>>();

    dim3 ggrid(T_STEPS / 128, GDIM / 128);        // (128, 32)
    gemm_tf32_kernel<<<ggrid, 256>>>(input, W_ih, b_ih, b_hh);

    lstm_kernel<<<NBLK, RTHREADS>>>(W_hh);

    final_kernel<<<1, 1024>>>(W_lin, b_lin, out);
}